// round 3
// baseline (speedup 1.0000x reference)
#include <cuda_runtime.h>
#include <cstdint>

// Problem constants: B=256, T=512, C=256, L=64, S=129
#define Bb 256
#define Tt 512
#define Cc 256
#define Ll 64

// Scratch: per-lane label log-prob pairs (log2 domain), and blank log-probs.
static __device__ float2 g_pair[(size_t)Bb * Tt * 32];  // 33.5 MB
static __device__ float  g_bl[(size_t)Bb * Tt];         // 512 KB
static __device__ float  g_loss[Bb];

__device__ __forceinline__ float ex2f_(float x) {
    float y; asm("ex2.approx.ftz.f32 %0, %1;" : "=f"(y) : "f"(x)); return y;
}
__device__ __forceinline__ float lg2f_(float x) {
    float y; asm("lg2.approx.f32 %0, %1;" : "=f"(y) : "f"(x)); return y;
}

#define NEGF   (-1e30f)
#define LOG2E  1.4426950408889634f
#define LN2    0.6931471805599453f

// log2-domain logaddexp: log2(2^a + 2^b)   (2 MUFU)
__device__ __forceinline__ float lse2(float a, float b) {
    float m = fmaxf(a, b);
    float d = fminf(a, b) - m;           // <= 0
    return m + lg2f_(1.0f + ex2f_(d));
}
// log2-domain 3-way with exact max/mid/min selection   (3 MUFU)
__device__ __forceinline__ float lse3(float a, float b, float c) {
    float t1 = fmaxf(a, b), t2 = fminf(a, b);
    float mx = fmaxf(t1, c);
    float md = fminf(t1, fmaxf(t2, c));
    float mn = fminf(t2, c);
    return mx + lg2f_(1.0f + ex2f_(md - mx) + ex2f_(mn - mx));
}

// ---------------------------------------------------------------------------
// Kernel 1: per-(b,t) log_softmax + gather of the needed log-probs into
// pair/blank layout (log2 domain). Warp per row, 8 warps per block.
// ---------------------------------------------------------------------------
__global__ void __launch_bounds__(256) k_logits(const float* __restrict__ logits,
                                                const int* __restrict__ targets) {
    __shared__ float rows[8][Cc];
    int wid  = threadIdx.x >> 5;
    int lane = threadIdx.x & 31;
    int w = blockIdx.x * 8 + wid;        // w in [0, B*T)
    int b = w >> 9;                      // T = 512
    const float4* __restrict__ r4 = (const float4*)(logits + (size_t)w * Cc);

    float4 va = r4[lane];
    float4 vb = r4[lane + 32];
    ((float4*)rows[wid])[lane]      = va;
    ((float4*)rows[wid])[lane + 32] = vb;

    float m = fmaxf(fmaxf(fmaxf(va.x, va.y), fmaxf(va.z, va.w)),
                    fmaxf(fmaxf(vb.x, vb.y), fmaxf(vb.z, vb.w)));
#pragma unroll
    for (int off = 16; off; off >>= 1)
        m = fmaxf(m, __shfl_xor_sync(0xffffffffu, m, off));
    float m2 = m * LOG2E;
    float s = ex2f_(va.x * LOG2E - m2) + ex2f_(va.y * LOG2E - m2)
            + ex2f_(va.z * LOG2E - m2) + ex2f_(va.w * LOG2E - m2)
            + ex2f_(vb.x * LOG2E - m2) + ex2f_(vb.y * LOG2E - m2)
            + ex2f_(vb.z * LOG2E - m2) + ex2f_(vb.w * LOG2E - m2);
#pragma unroll
    for (int off = 16; off; off >>= 1)
        s += __shfl_xor_sync(0xffffffffu, s, off);
    float base2 = m2 + lg2f_(s);         // log2(sum exp) of the row

    __syncwarp();
    int2 tg2 = ((const int2*)(targets + b * Ll))[lane];
    float lp1 = rows[wid][tg2.x] * LOG2E - base2;
    float lp3 = rows[wid][tg2.y] * LOG2E - base2;
    g_pair[(size_t)w * 32 + lane] = make_float2(lp1, lp3);
    if (lane == 0)
        g_bl[w] = rows[wid][0] * LOG2E - base2;
}

// ---------------------------------------------------------------------------
// Kernel 2: CTC forward DP. One warp per batch row, states s=4*lane+k,
// s=128 as an extra scalar on lane 31. Depth-4 register prefetch ring.
// ---------------------------------------------------------------------------
__global__ void __launch_bounds__(64) k_dp(const int* __restrict__ targets,
                                           const int* __restrict__ in_len,
                                           const int* __restrict__ tg_len) {
    __shared__ float As[2][132];
    int wid  = threadIdx.x >> 5;
    int lane = threadIdx.x & 31;
    int b = blockIdx.x * 2 + wid;

    int2 tg2 = ((const int2*)(targets + b * Ll))[lane];
    int t1 = tg2.x, t3 = tg2.y;
    int tprev = __shfl_up_sync(0xffffffffu, t3, 1);  // tg[2*lane-1]
    bool skip1 = (lane > 0) && (t1 != tprev);
    bool skip3 = (t3 != t1);

    int Tin = in_len[b];
    int tl  = tg_len[b];
    const float2* __restrict__ pp = g_pair + (size_t)b * Tt * 32 + lane;
    const float*  __restrict__ bb = g_bl + (size_t)b * Tt;

    float a0 = NEGF, a1 = NEGF, a2 = NEGF, a3 = NEGF, aT = NEGF;
    {
        float2 p0 = __ldg(pp);
        float  b0 = __ldg(bb);
        if (lane == 0) { a0 = b0; a1 = p0.x; }       // alpha at t=0
    }

    // depth-4 prefetch ring
    float2 P[4]; float BL[4];
#pragma unroll
    for (int k = 0; k < 4; k++) {
        int t = 1 + k;
        P[k]  = __ldg(pp + (size_t)t * 32);
        BL[k] = __ldg(bb + t);
    }

#pragma unroll 4
    for (int t = 1; t < Tin; t++) {
        int k = (t - 1) & 3;
        float2 lp = P[k];
        float  bl = BL[k];
        int tn = t + 4;
        if (tn < Tt) {
            P[k]  = __ldg(pp + (size_t)tn * 32);
            BL[k] = __ldg(bb + tn);
        }

        float p3 = __shfl_up_sync(0xffffffffu, a3, 1);  // prev lane's s=4l-1
        if (lane == 0) p3 = NEGF;

        float n0 = lse2(a0, p3) + bl;                            // s=4l (blank)
        float n1 = lse3(a1, a0, skip1 ? p3 : NEGF) + lp.x;       // s=4l+1
        float n2 = lse2(a2, a1) + bl;                            // s=4l+2 (blank)
        float n3 = lse3(a3, a2, skip3 ? a1 : NEGF) + lp.y;       // s=4l+3
        float nT = lse2(aT, a3) + bl;                            // s=128 (lane31)

        a0 = fmaxf(n0, NEGF);
        a1 = fmaxf(n1, NEGF);
        a2 = fmaxf(n2, NEGF);
        a3 = fmaxf(n3, NEGF);
        aT = fmaxf(nT, NEGF);
    }

    As[wid][lane * 4 + 0] = a0;
    As[wid][lane * 4 + 1] = a1;
    As[wid][lane * 4 + 2] = a2;
    As[wid][lane * 4 + 3] = a3;
    if (lane == 31) As[wid][128] = aT;
    __syncwarp();

    if (lane == 0) {
        float fa = As[wid][2 * tl];
        float fb = As[wid][2 * tl - 1];
        float loss = -LN2 * lse2(fa, fb);    // back to natural log
        if (!(loss <= 1e20f)) loss = 0.0f;   // zero_infinity
        g_loss[b] = loss / (float)tl;
    }
}

// ---------------------------------------------------------------------------
// Kernel 3: deterministic mean over batch -> scalar output
// ---------------------------------------------------------------------------
__global__ void __launch_bounds__(256) k_red(float* __restrict__ out) {
    __shared__ float sh[256];
    int tid = threadIdx.x;
    sh[tid] = g_loss[tid];
    __syncthreads();
#pragma unroll
    for (int off = 128; off; off >>= 1) {
        if (tid < off) sh[tid] += sh[tid + off];
        __syncthreads();
    }
    if (tid == 0) out[0] = sh[0] * (1.0f / 256.0f);
}

extern "C" void kernel_launch(void* const* d_in, const int* in_sizes, int n_in,
                              void* d_out, int out_size) {
    const float* logits  = (const float*)d_in[0];   // [B,T,C] f32
    const int*   targets = (const int*)d_in[1];     // [B,L] i32
    const int*   in_len  = (const int*)d_in[2];     // [B] i32
    const int*   tg_len  = (const int*)d_in[3];     // [B] i32

    k_logits<<<(Bb * Tt) / 8, 256>>>(logits, targets);
    k_dp<<<Bb / 2, 64>>>(targets, in_len, tg_len);
    k_red<<<1, 256>>>((float*)d_out);
}

// round 10
// speedup vs baseline: 2.5911x; 2.5911x over previous
#include <cuda_runtime.h>
#include <cstdint>

// Problem constants: B=256, T=512, C=256, L=64, S=129
#define Bb 256
#define Tt 512
#define Cc 256
#define Ll 64

// Scratch: per-lane label LINEAR-prob pairs, and blank linear probs.
static __device__ float2 g_pair[(size_t)Bb * Tt * 32];  // 33.5 MB
static __device__ float  g_bl[(size_t)Bb * Tt];         // 512 KB
static __device__ float  g_loss[Bb];

__device__ __forceinline__ float ex2f_(float x) {
    float y; asm("ex2.approx.ftz.f32 %0, %1;" : "=f"(y) : "f"(x)); return y;
}
__device__ __forceinline__ float lg2f_(float x) {
    float y; asm("lg2.approx.f32 %0, %1;" : "=f"(y) : "f"(x)); return y;
}

#define LOG2E  1.4426950408889634f
#define LN2    0.6931471805599453f

// ---------------------------------------------------------------------------
// Kernel 1: per-(b,t) softmax + gather of needed probabilities (LINEAR domain)
// into pair/blank layout. Warp per row, 8 warps per block.
// Label probs for garbage label indices (>= tg_len[b]) are zeroed so the DP
// never grows mass in states the reference doesn't read (they would otherwise
// dominate the rescale max and flush the real answer states to zero).
// ---------------------------------------------------------------------------
__global__ void __launch_bounds__(256) k_logits(const float* __restrict__ logits,
                                                const int* __restrict__ targets,
                                                const int* __restrict__ tg_len) {
    __shared__ float rows[8][Cc];
    int wid  = threadIdx.x >> 5;
    int lane = threadIdx.x & 31;
    int w = blockIdx.x * 8 + wid;        // w in [0, B*T)
    int b = w >> 9;                      // T = 512
    const float4* __restrict__ r4 = (const float4*)(logits + (size_t)w * Cc);

    float4 va = r4[lane];
    float4 vb = r4[lane + 32];
    ((float4*)rows[wid])[lane]      = va;
    ((float4*)rows[wid])[lane + 32] = vb;

    float m = fmaxf(fmaxf(fmaxf(va.x, va.y), fmaxf(va.z, va.w)),
                    fmaxf(fmaxf(vb.x, vb.y), fmaxf(vb.z, vb.w)));
#pragma unroll
    for (int off = 16; off; off >>= 1)
        m = fmaxf(m, __shfl_xor_sync(0xffffffffu, m, off));
    float m2 = m * LOG2E;
    float s = ex2f_(va.x * LOG2E - m2) + ex2f_(va.y * LOG2E - m2)
            + ex2f_(va.z * LOG2E - m2) + ex2f_(va.w * LOG2E - m2)
            + ex2f_(vb.x * LOG2E - m2) + ex2f_(vb.y * LOG2E - m2)
            + ex2f_(vb.z * LOG2E - m2) + ex2f_(vb.w * LOG2E - m2);
#pragma unroll
    for (int off = 16; off; off >>= 1)
        s += __shfl_xor_sync(0xffffffffu, s, off);
    float base2 = m2 + lg2f_(s);         // log2(sum exp) of the row

    __syncwarp();
    int tl = tg_len[b];
    int2 tg2 = ((const int2*)(targets + b * Ll))[lane];
    // linear probabilities p = 2^(x*log2e - base2), p <= 1
    float p1 = ex2f_(rows[wid][tg2.x] * LOG2E - base2);
    float p3 = ex2f_(rows[wid][tg2.y] * LOG2E - base2);
    if (2 * lane     >= tl) p1 = 0.0f;   // garbage label -> dead state
    if (2 * lane + 1 >= tl) p3 = 0.0f;
    g_pair[(size_t)w * 32 + lane] = make_float2(p1, p3);
    if (lane == 0)
        g_bl[w] = ex2f_(rows[wid][0] * LOG2E - base2);
}

// ---------------------------------------------------------------------------
// Kernel 2: CTC forward DP in LINEAR domain with power-of-2 rescaling.
// One warp per batch row, states s=4*lane+k, s=128 extra on lane 31.
// 8-step chunks: all loads for next chunk issued up front (double buffer),
// rescale to max=2^90 after each chunk (exact pow2 scaling, exponent in S).
// ---------------------------------------------------------------------------
__global__ void __launch_bounds__(64) k_dp(const int* __restrict__ targets,
                                           const int* __restrict__ in_len,
                                           const int* __restrict__ tg_len) {
    __shared__ float As[2][132];
    int wid  = threadIdx.x >> 5;
    int lane = threadIdx.x & 31;
    int b = blockIdx.x * 2 + wid;

    int2 tg2 = ((const int2*)(targets + b * Ll))[lane];
    int t1 = tg2.x, t3 = tg2.y;
    int tprev = __shfl_up_sync(0xffffffffu, t3, 1);  // tg[2*lane-1]
    float s1f = ((lane > 0) && (t1 != tprev)) ? 1.0f : 0.0f;
    float s3f = (t3 != t1) ? 1.0f : 0.0f;

    int Tin = in_len[b];
    int tl  = tg_len[b];
    const float2* __restrict__ pp = g_pair + (size_t)b * Tt * 32 + lane;
    const float*  __restrict__ bb = g_bl + (size_t)b * Tt;

    // init at t=0 (linear probs)
    float a0 = 0.f, a1 = 0.f, a2 = 0.f, a3 = 0.f, aT = 0.f;
    {
        float2 p0 = __ldg(pp);
        float  b0 = __ldg(bb);
        if (lane == 0) { a0 = b0; a1 = p0.x; }
    }
    int S = 0;   // stored = true * 2^S

    // load first chunk (t = 1..8)
    float2 P[8]; float BL[8];
#pragma unroll
    for (int k = 0; k < 8; k++) {
        P[k]  = __ldg(pp + (size_t)(1 + k) * 32);
        BL[k] = __ldg(bb + 1 + k);
    }

#define STEP(lp, bl)                                                     \
    {                                                                    \
        float p3 = __shfl_up_sync(0xffffffffu, a3, 1);                   \
        p3 = (lane == 0) ? 0.0f : p3;                                    \
        float n0 = (a0 + p3) * (bl);                                     \
        float n1 = fmaf(s1f, p3, a0 + a1) * (lp).x;                      \
        float n2 = (a1 + a2) * (bl);                                     \
        float n3 = fmaf(s3f, a1, a2 + a3) * (lp).y;                      \
        float nT = (a3 + aT) * (bl);                                     \
        a0 = n0; a1 = n1; a2 = n2; a3 = n3; aT = nT;                     \
    }

    int t = 1;
    for (; t + 8 <= Tin; t += 8) {
        // prefetch next chunk (clamped per element; always legal, unused past Tin)
        float2 Pn[8]; float BLn[8];
#pragma unroll
        for (int k = 0; k < 8; k++) {
            int idx = t + 8 + k; idx = (idx > Tt - 1) ? (Tt - 1) : idx;
            Pn[k]  = __ldg(pp + (size_t)idx * 32);
            BLn[k] = __ldg(bb + idx);
        }
#pragma unroll
        for (int k = 0; k < 8; k++) STEP(P[k], BL[k]);
#pragma unroll
        for (int k = 0; k < 8; k++) { P[k] = Pn[k]; BL[k] = BLn[k]; }

        // rescale: bring warp-max to 2^90 with an exact power-of-2 factor
        float mx = fmaxf(fmaxf(fmaxf(a0, a1), fmaxf(a2, a3)), aT);
        unsigned umx = __reduce_max_sync(0xffffffffu, __float_as_uint(mx));
        int ex = (int)(umx >> 23) & 255;     // biased exponent of warp max
        int h  = 217 - ex;                    // boost so max -> 2^90
        int h1 = h >> 1, h2 = h - h1;         // split so each factor is in range
        float sA = __uint_as_float((unsigned)(127 + h1) << 23);
        float sB = __uint_as_float((unsigned)(127 + h2) << 23);
        a0 = a0 * sA * sB; a1 = a1 * sA * sB; a2 = a2 * sA * sB;
        a3 = a3 * sA * sB; aT = aT * sA * sB;
        S += h;
    }
    // tail (<8 steps, no rescale needed)
    for (int k = 0; t < Tin; t++, k++) STEP(P[k], BL[k]);
#undef STEP

    As[wid][lane * 4 + 0] = a0;
    As[wid][lane * 4 + 1] = a1;
    As[wid][lane * 4 + 2] = a2;
    As[wid][lane * 4 + 3] = a3;
    if (lane == 31) As[wid][128] = aT;
    __syncwarp();

    if (lane == 0) {
        float fa = As[wid][2 * tl];
        float fb = As[wid][2 * tl - 1];
        float sum = fa + fb;                       // linear logaddexp
        // log(alpha_true) = ln2 * (log2(stored) - S)
        float loss = LN2 * ((float)S - lg2f_(sum));
        if (!(loss <= 1e20f)) loss = 0.0f;         // zero_infinity (also sum==0)
        g_loss[b] = loss / (float)tl;
    }
}

// ---------------------------------------------------------------------------
// Kernel 3: deterministic mean over batch -> scalar output
// ---------------------------------------------------------------------------
__global__ void __launch_bounds__(256) k_red(float* __restrict__ out) {
    __shared__ float sh[256];
    int tid = threadIdx.x;
    sh[tid] = g_loss[tid];
    __syncthreads();
#pragma unroll
    for (int off = 128; off; off >>= 1) {
        if (tid < off) sh[tid] += sh[tid + off];
        __syncthreads();
    }
    if (tid == 0) out[0] = sh[0] * (1.0f / 256.0f);
}

extern "C" void kernel_launch(void* const* d_in, const int* in_sizes, int n_in,
                              void* d_out, int out_size) {
    const float* logits  = (const float*)d_in[0];   // [B,T,C] f32
    const int*   targets = (const int*)d_in[1];     // [B,L] i32
    const int*   in_len  = (const int*)d_in[2];     // [B] i32
    const int*   tg_len  = (const int*)d_in[3];     // [B] i32

    k_logits<<<(Bb * Tt) / 8, 256>>>(logits, targets, tg_len);
    k_dp<<<Bb / 2, 64>>>(targets, in_len, tg_len);
    k_red<<<1, 256>>>((float*)d_out);
}

// round 11
// speedup vs baseline: 2.8895x; 1.1152x over previous
#include <cuda_runtime.h>
#include <cstdint>

// Problem constants: B=256, T=512, C=256, L=64, S=129
#define Bb 256
#define Tt 512
#define Cc 256
#define Ll 64

// Scratch: per-lane label LINEAR-prob pairs, and blank linear probs.
static __device__ float2 g_pair[(size_t)Bb * Tt * 32];  // 33.5 MB
static __device__ float  g_bl[(size_t)Bb * Tt];         // 512 KB
static __device__ float  g_loss[Bb];
static __device__ int    g_cnt = 0;

__device__ __forceinline__ float ex2f_(float x) {
    float y; asm("ex2.approx.ftz.f32 %0, %1;" : "=f"(y) : "f"(x)); return y;
}
__device__ __forceinline__ float lg2f_(float x) {
    float y; asm("lg2.approx.f32 %0, %1;" : "=f"(y) : "f"(x)); return y;
}

#define LOG2E  1.4426950408889634f
#define LN2    0.6931471805599453f

// ---------------------------------------------------------------------------
// Kernel 1: per-(b,t) softmax + gather of needed probabilities (LINEAR domain)
// into pair/blank layout. Warp per row, 8 warps per block.
// Label probs for garbage label indices (>= tg_len[b]) are zeroed so dead
// states never accumulate mass (they'd poison the rescale max otherwise).
// ---------------------------------------------------------------------------
__global__ void __launch_bounds__(256) k_logits(const float* __restrict__ logits,
                                                const int* __restrict__ targets,
                                                const int* __restrict__ tg_len) {
    __shared__ float rows[8][Cc];
    int wid  = threadIdx.x >> 5;
    int lane = threadIdx.x & 31;
    int w = blockIdx.x * 8 + wid;        // w in [0, B*T)
    int b = w >> 9;                      // T = 512
    const float4* __restrict__ r4 = (const float4*)(logits + (size_t)w * Cc);

    float4 va = r4[lane];
    float4 vb = r4[lane + 32];
    ((float4*)rows[wid])[lane]      = va;
    ((float4*)rows[wid])[lane + 32] = vb;

    float m = fmaxf(fmaxf(fmaxf(va.x, va.y), fmaxf(va.z, va.w)),
                    fmaxf(fmaxf(vb.x, vb.y), fmaxf(vb.z, vb.w)));
#pragma unroll
    for (int off = 16; off; off >>= 1)
        m = fmaxf(m, __shfl_xor_sync(0xffffffffu, m, off));
    float m2 = m * LOG2E;
    float s = ex2f_(va.x * LOG2E - m2) + ex2f_(va.y * LOG2E - m2)
            + ex2f_(va.z * LOG2E - m2) + ex2f_(va.w * LOG2E - m2)
            + ex2f_(vb.x * LOG2E - m2) + ex2f_(vb.y * LOG2E - m2)
            + ex2f_(vb.z * LOG2E - m2) + ex2f_(vb.w * LOG2E - m2);
#pragma unroll
    for (int off = 16; off; off >>= 1)
        s += __shfl_xor_sync(0xffffffffu, s, off);
    float base2 = m2 + lg2f_(s);         // log2(sum exp) of the row

    __syncwarp();
    int tl = tg_len[b];
    int2 tg2 = ((const int2*)(targets + b * Ll))[lane];
    float p1 = ex2f_(rows[wid][tg2.x] * LOG2E - base2);
    float p3 = ex2f_(rows[wid][tg2.y] * LOG2E - base2);
    if (2 * lane     >= tl) p1 = 0.0f;   // garbage label -> dead state
    if (2 * lane + 1 >= tl) p3 = 0.0f;
    g_pair[(size_t)w * 32 + lane] = make_float2(p1, p3);
    if (lane == 0)
        g_bl[w] = ex2f_(rows[wid][0] * LOG2E - base2);
}

// ---------------------------------------------------------------------------
// Kernel 2: CTC forward DP in LINEAR domain with power-of-2 rescaling.
// One warp per batch row, states s=4*lane+k, s=128 extra on lane 31.
// 3-deep chunk pipeline (24-step grand loop, three 8-step register buffers):
// ~2.3 chunks (~450+ cyc) of prefetch distance covers DRAM latency.
// Final mean fused in via last-block pattern.
// ---------------------------------------------------------------------------
__global__ void __launch_bounds__(64) k_dp(const int* __restrict__ targets,
                                           const int* __restrict__ in_len,
                                           const int* __restrict__ tg_len,
                                           float* __restrict__ out) {
    __shared__ float As[2][132];
    __shared__ int   s_last;
    int tid  = threadIdx.x;
    int wid  = tid >> 5;
    int lane = tid & 31;
    int b = blockIdx.x * 2 + wid;

    int2 tg2 = ((const int2*)(targets + b * Ll))[lane];
    int t1 = tg2.x, t3 = tg2.y;
    int tprev = __shfl_up_sync(0xffffffffu, t3, 1);  // tg[2*lane-1]
    float s1f = ((lane > 0) && (t1 != tprev)) ? 1.0f : 0.0f;
    float s3f = (t3 != t1) ? 1.0f : 0.0f;

    int Tin = in_len[b];
    int tl  = tg_len[b];
    const float2* __restrict__ pp = g_pair + (size_t)b * Tt * 32 + lane;
    const float*  __restrict__ bb = g_bl + (size_t)b * Tt;

    // init at t=0 (linear probs)
    float a0 = 0.f, a1 = 0.f, a2 = 0.f, a3 = 0.f, aT = 0.f;
    {
        float2 p0 = __ldg(pp);
        float  b0 = __ldg(bb);
        if (lane == 0) { a0 = b0; a1 = p0.x; }
    }
    int S = 0;   // stored = true * 2^S

    float2 PA[8], PB[8], PC[8];
    float  BA[8], BBf[8], BC[8];

#define PREF(P_, B_, base)                                               \
    {                                                                    \
        _Pragma("unroll")                                                \
        for (int k = 0; k < 8; k++) {                                    \
            int idx = (base) + k; idx = (idx > Tt - 1) ? (Tt - 1) : idx; \
            P_[k] = __ldg(pp + (size_t)idx * 32);                        \
            B_[k] = __ldg(bb + idx);                                     \
        }                                                                \
    }

#define STEP(lp, bl)                                                     \
    {                                                                    \
        float p3 = __shfl_up_sync(0xffffffffu, a3, 1);                   \
        p3 = (lane == 0) ? 0.0f : p3;                                    \
        float n0 = (a0 + p3) * (bl);                                     \
        float n1 = fmaf(s1f, p3, a0 + a1) * (lp).x;                      \
        float n2 = (a1 + a2) * (bl);                                     \
        float n3 = fmaf(s3f, a1, a2 + a3) * (lp).y;                      \
        float nT = (a3 + aT) * (bl);                                     \
        a0 = n0; a1 = n1; a2 = n2; a3 = n3; aT = nT;                     \
    }

#define RESCALE                                                          \
    {                                                                    \
        float mx = fmaxf(fmaxf(fmaxf(a0, a1), fmaxf(a2, a3)), aT);       \
        unsigned umx = __reduce_max_sync(0xffffffffu, __float_as_uint(mx)); \
        int ex = (int)(umx >> 23) & 255;                                 \
        int h  = 217 - ex;                                               \
        int h1 = h >> 1, h2 = h - h1;                                    \
        float sA = __uint_as_float((unsigned)(127 + h1) << 23);          \
        float sB = __uint_as_float((unsigned)(127 + h2) << 23);          \
        a0 = a0 * sA * sB; a1 = a1 * sA * sB; a2 = a2 * sA * sB;         \
        a3 = a3 * sA * sB; aT = aT * sA * sB;                            \
        S += h;                                                          \
    }

#define PROC8(P_, B_)                                                    \
    {                                                                    \
        _Pragma("unroll")                                                \
        for (int k = 0; k < 8; k++) STEP(P_[k], B_[k]);                  \
    }

    // preload 3 chunks: t = 1..8, 9..16, 17..24
    PREF(PA, BA, 1);
    PREF(PB, BBf, 9);
    PREF(PC, BC, 17);

    int t = 1;
    for (; t + 24 <= Tin; t += 24) {
        PROC8(PA, BA);  RESCALE;  PREF(PA, BA,  t + 24);
        PROC8(PB, BBf); RESCALE;  PREF(PB, BBf, t + 32);
        PROC8(PC, BC);  RESCALE;  PREF(PC, BC,  t + 40);
    }
    // tail (< 24 steps); rescale between sub-chunks (safe even after freeze)
    for (int k = 0; k < 8 && t < Tin; k++, t++) STEP(PA[k], BA[k]);
    RESCALE;
    for (int k = 0; k < 8 && t < Tin; k++, t++) STEP(PB[k], BBf[k]);
    RESCALE;
    for (int k = 0; k < 8 && t < Tin; k++, t++) STEP(PC[k], BC[k]);
#undef STEP
#undef PREF
#undef PROC8
#undef RESCALE

    As[wid][lane * 4 + 0] = a0;
    As[wid][lane * 4 + 1] = a1;
    As[wid][lane * 4 + 2] = a2;
    As[wid][lane * 4 + 3] = a3;
    if (lane == 31) As[wid][128] = aT;
    __syncwarp();

    if (lane == 0) {
        float fa = As[wid][2 * tl];
        float fb = As[wid][2 * tl - 1];
        float sum = fa + fb;                       // linear logaddexp
        float loss = LN2 * ((float)S - lg2f_(sum));
        if (!(loss <= 1e20f)) loss = 0.0f;         // zero_infinity (also sum==0)
        g_loss[b] = loss / (float)tl;
    }

    // ---- fused deterministic mean: last block to arrive reduces g_loss ----
    __syncthreads();
    __threadfence();
    if (tid == 0) {
        int rank = atomicAdd(&g_cnt, 1);
        s_last = (rank == (int)gridDim.x - 1) ? 1 : 0;
    }
    __syncthreads();
    if (s_last) {
        __threadfence();                 // acquire: see all g_loss writes
        __shared__ float sh[64];
        float v = g_loss[tid * 4 + 0] + g_loss[tid * 4 + 1]
                + g_loss[tid * 4 + 2] + g_loss[tid * 4 + 3];
        sh[tid] = v;
        __syncthreads();
#pragma unroll
        for (int off = 32; off; off >>= 1) {
            if (tid < off) sh[tid] += sh[tid + off];
            __syncthreads();
        }
        if (tid == 0) {
            out[0] = sh[0] * (1.0f / 256.0f);
            g_cnt = 0;                   // reset for next graph replay
        }
    }
}

extern "C" void kernel_launch(void* const* d_in, const int* in_sizes, int n_in,
                              void* d_out, int out_size) {
    const float* logits  = (const float*)d_in[0];   // [B,T,C] f32
    const int*   targets = (const int*)d_in[1];     // [B,L] i32
    const int*   in_len  = (const int*)d_in[2];     // [B] i32
    const int*   tg_len  = (const int*)d_in[3];     // [B] i32

    k_logits<<<(Bb * Tt) / 8, 256>>>(logits, targets, tg_len);
    k_dp<<<Bb / 2, 64>>>(targets, in_len, tg_len, (float*)d_out);
}

// round 12
// speedup vs baseline: 3.6980x; 1.2798x over previous
#include <cuda_runtime.h>
#include <cstdint>

// Problem constants: B=256, T=512, C=256, L=64, S=129
#define Bb 256
#define Tt 512
#define Cc 256
#define Ll 64

// Scratch: per-lane label LINEAR-prob pairs, and blank linear probs.
static __device__ float2 g_pair[(size_t)Bb * Tt * 32];  // 33.5 MB
static __device__ float  g_bl[(size_t)Bb * Tt];         // 512 KB
static __device__ float  g_loss[Bb];
static __device__ int    g_cnt = 0;

__device__ __forceinline__ float ex2f_(float x) {
    float y; asm("ex2.approx.ftz.f32 %0, %1;" : "=f"(y) : "f"(x)); return y;
}
__device__ __forceinline__ float lg2f_(float x) {
    float y; asm("lg2.approx.f32 %0, %1;" : "=f"(y) : "f"(x)); return y;
}

#define LOG2E  1.4426950408889634f
#define LN2    0.6931471805599453f

// ---------------------------------------------------------------------------
// Kernel 1: per-(b,t) softmax + gather of needed probabilities (LINEAR domain)
// into pair/blank layout. Warp per row, 8 warps per block.
// Logits are read with streaming (evict-first) hint so the one-pass 134MB
// stream does NOT evict the 34MB g_pair scratch from L2 — k_dp then reads
// g_pair at L2 latency instead of DRAM latency.
// Label probs for garbage label indices (>= tg_len[b]) are zeroed so dead
// states never accumulate mass (they'd poison the rescale max otherwise).
// ---------------------------------------------------------------------------
__global__ void __launch_bounds__(256) k_logits(const float* __restrict__ logits,
                                                const int* __restrict__ targets,
                                                const int* __restrict__ tg_len) {
    __shared__ float rows[8][Cc];
    int wid  = threadIdx.x >> 5;
    int lane = threadIdx.x & 31;
    int w = blockIdx.x * 8 + wid;        // w in [0, B*T)
    int b = w >> 9;                      // T = 512
    const float4* __restrict__ r4 = (const float4*)(logits + (size_t)w * Cc);

    float4 va = __ldcs(r4 + lane);       // streaming: evict-first in L2
    float4 vb = __ldcs(r4 + lane + 32);
    ((float4*)rows[wid])[lane]      = va;
    ((float4*)rows[wid])[lane + 32] = vb;

    float m = fmaxf(fmaxf(fmaxf(va.x, va.y), fmaxf(va.z, va.w)),
                    fmaxf(fmaxf(vb.x, vb.y), fmaxf(vb.z, vb.w)));
#pragma unroll
    for (int off = 16; off; off >>= 1)
        m = fmaxf(m, __shfl_xor_sync(0xffffffffu, m, off));
    float m2 = m * LOG2E;
    float s = ex2f_(va.x * LOG2E - m2) + ex2f_(va.y * LOG2E - m2)
            + ex2f_(va.z * LOG2E - m2) + ex2f_(va.w * LOG2E - m2)
            + ex2f_(vb.x * LOG2E - m2) + ex2f_(vb.y * LOG2E - m2)
            + ex2f_(vb.z * LOG2E - m2) + ex2f_(vb.w * LOG2E - m2);
#pragma unroll
    for (int off = 16; off; off >>= 1)
        s += __shfl_xor_sync(0xffffffffu, s, off);
    float base2 = m2 + lg2f_(s);         // log2(sum exp) of the row

    __syncwarp();
    int tl = tg_len[b];
    int2 tg2 = ((const int2*)(targets + b * Ll))[lane];
    float p1 = ex2f_(rows[wid][tg2.x] * LOG2E - base2);
    float p3 = ex2f_(rows[wid][tg2.y] * LOG2E - base2);
    if (2 * lane     >= tl) p1 = 0.0f;   // garbage label -> dead state
    if (2 * lane + 1 >= tl) p3 = 0.0f;
    g_pair[(size_t)w * 32 + lane] = make_float2(p1, p3);
    if (lane == 0)
        g_bl[w] = ex2f_(rows[wid][0] * LOG2E - base2);
}

// ---------------------------------------------------------------------------
// Kernel 2: CTC forward DP in LINEAR domain with power-of-2 rescaling.
// One warp per batch row, states s=4*lane+k, s=128 extra on lane 31.
// 4-deep chunk pipeline (32-step grand loop, four 8-step register buffers):
// 24-32 step prefetch distance (~700-950 cyc of compute) covers L2/DRAM
// latency at NAT clock. Final mean fused in via last-block pattern.
// ---------------------------------------------------------------------------
__global__ void __launch_bounds__(64) k_dp(const int* __restrict__ targets,
                                           const int* __restrict__ in_len,
                                           const int* __restrict__ tg_len,
                                           float* __restrict__ out) {
    __shared__ float As[2][132];
    __shared__ int   s_last;
    int tid  = threadIdx.x;
    int wid  = tid >> 5;
    int lane = tid & 31;
    int b = blockIdx.x * 2 + wid;

    int2 tg2 = ((const int2*)(targets + b * Ll))[lane];
    int t1 = tg2.x, t3 = tg2.y;
    int tprev = __shfl_up_sync(0xffffffffu, t3, 1);  // tg[2*lane-1]
    float s1f = ((lane > 0) && (t1 != tprev)) ? 1.0f : 0.0f;
    float s3f = (t3 != t1) ? 1.0f : 0.0f;

    int Tin = in_len[b];
    int tl  = tg_len[b];
    const float2* __restrict__ pp = g_pair + (size_t)b * Tt * 32 + lane;
    const float*  __restrict__ bb = g_bl + (size_t)b * Tt;

    // init at t=0 (linear probs)
    float a0 = 0.f, a1 = 0.f, a2 = 0.f, a3 = 0.f, aT = 0.f;
    {
        float2 p0 = __ldg(pp);
        float  b0 = __ldg(bb);
        if (lane == 0) { a0 = b0; a1 = p0.x; }
    }
    int S = 0;   // stored = true * 2^S

    float2 PA[8], PB[8], PC[8], PD[8];
    float  BA[8], BBf[8], BC[8], BD[8];

#define PREF(P_, B_, base)                                               \
    {                                                                    \
        _Pragma("unroll")                                                \
        for (int k = 0; k < 8; k++) {                                    \
            int idx = (base) + k; idx = (idx > Tt - 1) ? (Tt - 1) : idx; \
            P_[k] = __ldg(pp + (size_t)idx * 32);                        \
            B_[k] = __ldg(bb + idx);                                     \
        }                                                                \
    }

#define STEP(lp, bl)                                                     \
    {                                                                    \
        float p3 = __shfl_up_sync(0xffffffffu, a3, 1);                   \
        p3 = (lane == 0) ? 0.0f : p3;                                    \
        float n0 = (a0 + p3) * (bl);                                     \
        float n1 = fmaf(s1f, p3, a0 + a1) * (lp).x;                      \
        float n2 = (a1 + a2) * (bl);                                     \
        float n3 = fmaf(s3f, a1, a2 + a3) * (lp).y;                      \
        float nT = (a3 + aT) * (bl);                                     \
        a0 = n0; a1 = n1; a2 = n2; a3 = n3; aT = nT;                     \
    }

#define RESCALE                                                          \
    {                                                                    \
        float mx = fmaxf(fmaxf(fmaxf(a0, a1), fmaxf(a2, a3)), aT);       \
        unsigned umx = __reduce_max_sync(0xffffffffu, __float_as_uint(mx)); \
        int ex = (int)(umx >> 23) & 255;                                 \
        int h  = 217 - ex;                                               \
        int h1 = h >> 1, h2 = h - h1;                                    \
        float sA = __uint_as_float((unsigned)(127 + h1) << 23);          \
        float sB = __uint_as_float((unsigned)(127 + h2) << 23);          \
        a0 = a0 * sA * sB; a1 = a1 * sA * sB; a2 = a2 * sA * sB;         \
        a3 = a3 * sA * sB; aT = aT * sA * sB;                            \
        S += h;                                                          \
    }

#define PROC8(P_, B_)                                                    \
    {                                                                    \
        _Pragma("unroll")                                                \
        for (int k = 0; k < 8; k++) STEP(P_[k], B_[k]);                  \
    }

    // preload 4 chunks: t = 1..8, 9..16, 17..24, 25..32
    PREF(PA, BA, 1);
    PREF(PB, BBf, 9);
    PREF(PC, BC, 17);
    PREF(PD, BD, 25);

    int t = 1;
    for (; t + 32 <= Tin; t += 32) {
        PROC8(PA, BA);  RESCALE;  PREF(PA, BA,  t + 32);
        PROC8(PB, BBf); RESCALE;  PREF(PB, BBf, t + 40);
        PROC8(PC, BC);  RESCALE;  PREF(PC, BC,  t + 48);
        PROC8(PD, BD);  RESCALE;  PREF(PD, BD,  t + 56);
    }
    // tail (< 32 steps); rescale between sub-chunks (safe even after freeze)
    for (int k = 0; k < 8 && t < Tin; k++, t++) STEP(PA[k], BA[k]);
    RESCALE;
    for (int k = 0; k < 8 && t < Tin; k++, t++) STEP(PB[k], BBf[k]);
    RESCALE;
    for (int k = 0; k < 8 && t < Tin; k++, t++) STEP(PC[k], BC[k]);
    RESCALE;
    for (int k = 0; k < 8 && t < Tin; k++, t++) STEP(PD[k], BD[k]);
#undef STEP
#undef PREF
#undef PROC8
#undef RESCALE

    As[wid][lane * 4 + 0] = a0;
    As[wid][lane * 4 + 1] = a1;
    As[wid][lane * 4 + 2] = a2;
    As[wid][lane * 4 + 3] = a3;
    if (lane == 31) As[wid][128] = aT;
    __syncwarp();

    if (lane == 0) {
        float fa = As[wid][2 * tl];
        float fb = As[wid][2 * tl - 1];
        float sum = fa + fb;                       // linear logaddexp
        float loss = LN2 * ((float)S - lg2f_(sum));
        if (!(loss <= 1e20f)) loss = 0.0f;         // zero_infinity (also sum==0)
        g_loss[b] = loss / (float)tl;
    }

    // ---- fused deterministic mean: last block to arrive reduces g_loss ----
    __syncthreads();
    __threadfence();
    if (tid == 0) {
        int rank = atomicAdd(&g_cnt, 1);
        s_last = (rank == (int)gridDim.x - 1) ? 1 : 0;
    }
    __syncthreads();
    if (s_last) {
        __threadfence();                 // acquire: see all g_loss writes
        __shared__ float sh[64];
        float v = g_loss[tid * 4 + 0] + g_loss[tid * 4 + 1]
                + g_loss[tid * 4 + 2] + g_loss[tid * 4 + 3];
        sh[tid] = v;
        __syncthreads();
#pragma unroll
        for (int off = 32; off; off >>= 1) {
            if (tid < off) sh[tid] += sh[tid + off];
            __syncthreads();
        }
        if (tid == 0) {
            out[0] = sh[0] * (1.0f / 256.0f);
            g_cnt = 0;                   // reset for next graph replay
        }
    }
}

extern "C" void kernel_launch(void* const* d_in, const int* in_sizes, int n_in,
                              void* d_out, int out_size) {
    const float* logits  = (const float*)d_in[0];   // [B,T,C] f32
    const int*   targets = (const int*)d_in[1];     // [B,L] i32
    const int*   in_len  = (const int*)d_in[2];     // [B] i32
    const int*   tg_len  = (const int*)d_in[3];     // [B] i32

    k_logits<<<(Bb * Tt) / 8, 256>>>(logits, targets, tg_len);
    k_dp<<<Bb / 2, 64>>>(targets, in_len, tg_len, (float*)d_out);
}

// round 14
// speedup vs baseline: 4.1110x; 1.1117x over previous
#include <cuda_runtime.h>
#include <cstdint>

// Problem constants: B=256, T=512, C=256, L=64, S=129
#define Bb 256
#define Tt 512
#define Cc 256
#define Ll 64

// Scratch: per-lane label LINEAR-prob pairs, and blank linear probs.
static __device__ float2 g_pair[(size_t)Bb * Tt * 32];  // 33.5 MB  [b][t][lane]
static __device__ float  g_bl[(size_t)Bb * Tt];         // 512 KB   [b][t]
static __device__ float  g_loss[Bb];
static __device__ int    g_cnt = 0;

__device__ __forceinline__ float ex2f_(float x) {
    float y; asm("ex2.approx.ftz.f32 %0, %1;" : "=f"(y) : "f"(x)); return y;
}
__device__ __forceinline__ float lg2f_(float x) {
    float y; asm("lg2.approx.f32 %0, %1;" : "=f"(y) : "f"(x)); return y;
}
__device__ __forceinline__ void cpa16(uint32_t dst, const void* src) {
    asm volatile("cp.async.cg.shared.global [%0], [%1], 16;" :: "r"(dst), "l"(src));
}
__device__ __forceinline__ void cpa4(uint32_t dst, const void* src) {
    asm volatile("cp.async.ca.shared.global [%0], [%1], 4;" :: "r"(dst), "l"(src));
}

#define LOG2E  1.4426950408889634f
#define LN2    0.6931471805599453f

// ---------------------------------------------------------------------------
// Kernel 1: per-(b,t) softmax + gather of needed probabilities (LINEAR domain)
// into pair/blank layout. Warp per row, 8 warps per block. Streaming loads on
// the one-pass logits so L2 keeps the scratch. Garbage labels (>= tg_len)
// zeroed so dead states never accumulate mass.
// ---------------------------------------------------------------------------
__global__ void __launch_bounds__(256) k_logits(const float* __restrict__ logits,
                                                const int* __restrict__ targets,
                                                const int* __restrict__ tg_len) {
    __shared__ float rows[8][Cc];
    int wid  = threadIdx.x >> 5;
    int lane = threadIdx.x & 31;
    int w = blockIdx.x * 8 + wid;        // w in [0, B*T)
    int b = w >> 9;                      // T = 512
    const float4* __restrict__ r4 = (const float4*)(logits + (size_t)w * Cc);

    float4 va = __ldcs(r4 + lane);       // streaming: evict-first in L2
    float4 vb = __ldcs(r4 + lane + 32);
    ((float4*)rows[wid])[lane]      = va;
    ((float4*)rows[wid])[lane + 32] = vb;

    float m = fmaxf(fmaxf(fmaxf(va.x, va.y), fmaxf(va.z, va.w)),
                    fmaxf(fmaxf(vb.x, vb.y), fmaxf(vb.z, vb.w)));
#pragma unroll
    for (int off = 16; off; off >>= 1)
        m = fmaxf(m, __shfl_xor_sync(0xffffffffu, m, off));
    float m2 = m * LOG2E;
    float s = ex2f_(va.x * LOG2E - m2) + ex2f_(va.y * LOG2E - m2)
            + ex2f_(va.z * LOG2E - m2) + ex2f_(va.w * LOG2E - m2)
            + ex2f_(vb.x * LOG2E - m2) + ex2f_(vb.y * LOG2E - m2)
            + ex2f_(vb.z * LOG2E - m2) + ex2f_(vb.w * LOG2E - m2);
#pragma unroll
    for (int off = 16; off; off >>= 1)
        s += __shfl_xor_sync(0xffffffffu, s, off);
    float base2 = m2 + lg2f_(s);         // log2(sum exp) of the row

    __syncwarp();
    int tl = tg_len[b];
    int2 tg2 = ((const int2*)(targets + b * Ll))[lane];
    float p1 = ex2f_(rows[wid][tg2.x] * LOG2E - base2);
    float p3 = ex2f_(rows[wid][tg2.y] * LOG2E - base2);
    if (2 * lane     >= tl) p1 = 0.0f;   // garbage label -> dead state
    if (2 * lane + 1 >= tl) p3 = 0.0f;
    g_pair[(size_t)w * 32 + lane] = make_float2(p1, p3);
    if (lane == 0)
        g_bl[w] = ex2f_(rows[wid][0] * LOG2E - base2);
}

// ---------------------------------------------------------------------------
// Kernel 2: CTC forward DP in LINEAR domain with power-of-2 rescaling.
// One warp per batch row, states s=4*lane+k, s=128 extra on lane 31.
// cp.async smem ring: 8 chunks x 8 steps (64-step prefetch distance, no
// LDG outstanding cap) -> DRAM latency fully covered. Mean fused at end.
// ---------------------------------------------------------------------------
__global__ void __launch_bounds__(64) k_dp(const int* __restrict__ targets,
                                           const int* __restrict__ in_len,
                                           const int* __restrict__ tg_len,
                                           float* __restrict__ out) {
    // ring: [warp][chunk%8][row][lane], one chunk = 8 rows x 256B = 2KB (contiguous)
    __shared__ __align__(16) float2 ring_p[2][8][8][32];   // 32 KB
    __shared__ float ring_b[2][8][8];                      // 512 B
    __shared__ float As[2][132];
    __shared__ int   s_last;

    int tid  = threadIdx.x;
    int wid  = tid >> 5;
    int lane = tid & 31;
    int b = blockIdx.x * 2 + wid;

    int2 tg2 = ((const int2*)(targets + b * Ll))[lane];
    int t1 = tg2.x, t3 = tg2.y;
    int tprev = __shfl_up_sync(0xffffffffu, t3, 1);  // tg[2*lane-1]
    float s1f = ((lane > 0) && (t1 != tprev)) ? 1.0f : 0.0f;
    float s3f = (t3 != t1) ? 1.0f : 0.0f;

    int Tin = in_len[b];
    int tl  = tg_len[b];
    const char* __restrict__ pbase = (const char*)(g_pair + (size_t)b * Tt * 32);
    const float* __restrict__ bb   = g_bl + (size_t)b * Tt;

    uint32_t p_u32 = (uint32_t)__cvta_generic_to_shared(&ring_p[wid][0][0][0]);
    uint32_t b_u32 = (uint32_t)__cvta_generic_to_shared(&ring_b[wid][0][0]);

    // issue prefetch for absolute chunk `cc` (t = 8*cc .. 8*cc+7); empty
    // commit past the end keeps group accounting aligned.
#define PREF_CHUNK(cc_)                                                  \
    {                                                                    \
        int cc = (cc_);                                                  \
        if (cc <= 63) {                                                  \
            const char* srcb = pbase + (size_t)cc * 2048;                \
            uint32_t dstb = p_u32 + (uint32_t)(cc & 7) * 2048;           \
            _Pragma("unroll")                                            \
            for (int i = 0; i < 4; i++)                                  \
                cpa16(dstb + i * 512 + lane * 16,                        \
                      srcb + i * 512 + lane * 16);                       \
            if (lane < 8)                                                \
                cpa4(b_u32 + (uint32_t)(cc & 7) * 32 + lane * 4,         \
                     (const void*)(bb + cc * 8 + lane));                 \
        }                                                                \
        asm volatile("cp.async.commit_group;");                          \
    }

#define STEP(lp, bl)                                                     \
    {                                                                    \
        float p3 = __shfl_up_sync(0xffffffffu, a3, 1);                   \
        p3 = (lane == 0) ? 0.0f : p3;                                    \
        float n0 = (a0 + p3) * (bl);                                     \
        float n1 = fmaf(s1f, p3, a0 + a1) * (lp).x;                      \
        float n2 = (a1 + a2) * (bl);                                     \
        float n3 = fmaf(s3f, a1, a2 + a3) * (lp).y;                      \
        float nT = (a3 + aT) * (bl);                                     \
        a0 = n0; a1 = n1; a2 = n2; a3 = n3; aT = nT;                     \
    }

#define RESCALE                                                          \
    {                                                                    \
        float mx = fmaxf(fmaxf(fmaxf(a0, a1), fmaxf(a2, a3)), aT);       \
        unsigned umx = __reduce_max_sync(0xffffffffu, __float_as_uint(mx)); \
        int ex = (int)(umx >> 23) & 255;                                 \
        int h  = 217 - ex;                                               \
        int h1 = h >> 1, h2 = h - h1;                                    \
        float sA = __uint_as_float((unsigned)(127 + h1) << 23);          \
        float sB = __uint_as_float((unsigned)(127 + h2) << 23);          \
        a0 = a0 * sA * sB; a1 = a1 * sA * sB; a2 = a2 * sA * sB;         \
        a3 = a3 * sA * sB; aT = aT * sA * sB;                            \
        S += h;                                                          \
    }

    float a0 = 0.f, a1 = 0.f, a2 = 0.f, a3 = 0.f, aT = 0.f;
    int S = 0;   // stored = true * 2^S

    // prologue: fill the ring (chunks 0..7)
#pragma unroll
    for (int c0 = 0; c0 < 8; c0++) PREF_CHUNK(c0);

    // chunk 0: init from row 0 (t=0), then steps t=1..7
    asm volatile("cp.async.wait_group 6;");
    __syncwarp();
    {
        float2 p00 = ring_p[wid][0][0][lane];
        float  bl0 = ring_b[wid][0][0];
        if (lane == 0) { a0 = bl0; a1 = p00.x; }
        float2 LPC[8]; float BLC[8];
#pragma unroll
        for (int k = 1; k < 8; k++) { LPC[k] = ring_p[wid][0][k][lane]; BLC[k] = ring_b[wid][0][k]; }
#pragma unroll
        for (int k = 1; k < 8; k++) STEP(LPC[k], BLC[k]);
    }
    RESCALE;
    PREF_CHUNK(8);

    // main: full chunks strictly below Tin
    int c = 1;
    for (; 8 * c + 8 <= Tin; c++) {
        asm volatile("cp.async.wait_group 6;");
        __syncwarp();
        int c7 = c & 7;
        float2 LPC[8]; float BLC[8];
#pragma unroll
        for (int k = 0; k < 8; k++) { LPC[k] = ring_p[wid][c7][k][lane]; BLC[k] = ring_b[wid][c7][k]; }
#pragma unroll
        for (int k = 0; k < 8; k++) STEP(LPC[k], BLC[k]);
        RESCALE;
        PREF_CHUNK(c + 8);
    }
    // tail chunk (t = 8c .. Tin-1)
    asm volatile("cp.async.wait_group 0;");
    __syncwarp();
    {
        int c7 = c & 7;
        for (int k = 0; 8 * c + k < Tin && k < 8; k++) {
            float2 lp = ring_p[wid][c7][k][lane];
            float  bl = ring_b[wid][c7][k];
            STEP(lp, bl);
        }
    }
#undef STEP
#undef PREF_CHUNK
#undef RESCALE

    As[wid][lane * 4 + 0] = a0;
    As[wid][lane * 4 + 1] = a1;
    As[wid][lane * 4 + 2] = a2;
    As[wid][lane * 4 + 3] = a3;
    if (lane == 31) As[wid][128] = aT;
    __syncwarp();

    if (lane == 0) {
        float fa = As[wid][2 * tl];
        float fb = As[wid][2 * tl - 1];
        float sum = fa + fb;                       // linear logaddexp
        float loss = LN2 * ((float)S - lg2f_(sum));
        if (!(loss <= 1e20f)) loss = 0.0f;         // zero_infinity (also sum==0)
        g_loss[b] = loss / (float)tl;
    }

    // ---- fused deterministic mean: last block to arrive reduces g_loss ----
    __syncthreads();
    __threadfence();
    if (tid == 0) {
        int rank = atomicAdd(&g_cnt, 1);
        s_last = (rank == (int)gridDim.x - 1) ? 1 : 0;
    }
    __syncthreads();
    if (s_last) {
        __threadfence();                 // acquire: see all g_loss writes
        __shared__ float sh[64];
        float v = g_loss[tid * 4 + 0] + g_loss[tid * 4 + 1]
                + g_loss[tid * 4 + 2] + g_loss[tid * 4 + 3];
        sh[tid] = v;
        __syncthreads();
#pragma unroll
        for (int off = 32; off; off >>= 1) {
            if (tid < off) sh[tid] += sh[tid + off];
            __syncthreads();
        }
        if (tid == 0) {
            out[0] = sh[0] * (1.0f / 256.0f);
            g_cnt = 0;                   // reset for next graph replay
        }
    }
}

extern "C" void kernel_launch(void* const* d_in, const int* in_sizes, int n_in,
                              void* d_out, int out_size) {
    const float* logits  = (const float*)d_in[0];   // [B,T,C] f32
    const int*   targets = (const int*)d_in[1];     // [B,L] i32
    const int*   in_len  = (const int*)d_in[2];     // [B] i32
    const int*   tg_len  = (const int*)d_in[3];     // [B] i32

    k_logits<<<(Bb * Tt) / 8, 256>>>(logits, targets, tg_len);
    k_dp<<<Bb / 2, 64>>>(targets, in_len, tg_len, (float*)d_out);
}